// round 2
// baseline (speedup 1.0000x reference)
#include <cuda_runtime.h>
#include <cuda_bf16.h>
#include <cstdint>

// Problem constants (from reference): B=128 batches, S=1024 steps, T=128 tags.
#define Bd 128
#define Sd 1024
#define Td 128

__device__ float g_den[Bd];
__device__ float g_num[Bd];

// ---------- packed f32x2 helpers (sm_100+) ----------
__device__ __forceinline__ unsigned long long pk2(float x, float y) {
    unsigned long long r;
    asm("mov.b64 %0, {%1, %2};" : "=l"(r) : "f"(x), "f"(y));
    return r;
}
__device__ __forceinline__ void upk2(unsigned long long v, float& x, float& y) {
    asm("mov.b64 {%0, %1}, %2;" : "=f"(x), "=f"(y) : "l"(v));
}
__device__ __forceinline__ unsigned long long ffma2(unsigned long long a,
                                                    unsigned long long b,
                                                    unsigned long long c) {
    unsigned long long d;
    asm("fma.rn.f32x2 %0, %1, %2, %3;" : "=l"(d) : "l"(a), "l"(b), "l"(c));
    return d;
}
__device__ __forceinline__ unsigned long long fadd2(unsigned long long a,
                                                    unsigned long long b) {
    unsigned long long d;
    asm("add.rn.f32x2 %0, %1, %2;" : "=l"(d) : "l"(a), "l"(b));
    return d;
}

// mask is delivered widened (bool -> int32 or float32): 4-byte nonzero test
// is correct for both encodings of "true" (1 and 0x3F800000).
__device__ __forceinline__ int mask_at(const int* __restrict__ m, int idx) {
    return m[idx] != 0 ? 1 : 0;
}

// =====================================================================
// Denominator kernel: one CTA per batch, 256 threads.
// Thread t: column j = t>>1, half h = t&1 (i-range [64h, 64h+64)).
// E[:, j] = exp(trans[:, j] - D_j) held packed in 32 x f32x2 registers.
// Per step: w_j = sum_i v_i * E_ij (f32x2 matvec, shfl-combined),
//           new_atil_j = logf(w_j) + D_j + logit_j - c,  Z += c,
//           v_j = expf(atil_j) stored to ping-pong smem buffer.
// =====================================================================
__global__ __launch_bounds__(256, 1) void crf_den_kernel(
    const float* __restrict__ inputs,
    const int* __restrict__ mask,
    const float* __restrict__ trans,
    const float* __restrict__ startt,
    const float* __restrict__ endt)
{
    __shared__ __align__(16) float sv[2][Td];   // v = exp(atil), ping-pong
    __shared__ float sshift[2];                 // atil_0 broadcast, ping-pong
    __shared__ unsigned char smask[Sd];
    __shared__ float red[Td];

    const int b   = blockIdx.x;
    const int tid = threadIdx.x;
    const int j   = tid >> 1;
    const int h   = tid & 1;
    const float* inp = inputs + (size_t)b * Sd * Td;

    // mask row -> smem (widened-bool-safe read)
    for (int i = tid; i < Sd; i += 256)
        smask[i] = (unsigned char)mask_at(mask, b * Sd + i);

    // D_j = max_i trans[i][j]
    float dj = -1e30f;
#pragma unroll 8
    for (int i = 0; i < Td; i++) dj = fmaxf(dj, __ldg(&trans[i * Td + j]));

    // E column (own i-half) packed into registers
    unsigned long long e2[32];
#pragma unroll
    for (int m = 0; m < 32; m++) {
        int i = h * 64 + 2 * m;
        float ea = __expf(__ldg(&trans[i * Td + j]) - dj);
        float eb = __expf(__ldg(&trans[(i + 1) * Td + j]) - dj);
        e2[m] = pk2(ea, eb);
    }

    // ---- init: alpha0 = start + inputs[:,0], shifted so atil_0 = 0 ----
    float atil = 0.f, Z = 0.f;
    if (h == 0) atil = startt[j] + inp[j];
    if (tid == 0) sshift[0] = atil;   // raw alpha0[0]
    __syncthreads();
    float a00 = sshift[0];
    if (h == 0) { atil -= a00; Z = a00; }
    __syncthreads();                   // before rewriting sshift[0]
    if (h == 0) sv[0][j] = __expf(atil);
    if (tid == 0) sshift[0] = atil;    // == 0

    // logit register prefetch queue (depth 4)
    auto LQ = [&](int s) -> float {
        int sc = s < Sd ? s : (Sd - 1);
        return __ldg(&inp[sc * Td + j]);
    };
    float lq0 = LQ(1), lq1 = LQ(2), lq2 = LQ(3), lq3 = LQ(4);

    auto STEP = [&](int s, float logit) {
        __syncthreads();  // v (read buffer) + sshift from previous region valid
        const float4* vv = reinterpret_cast<const float4*>(sv[(s - 1) & 1]) + h * 16;
        unsigned long long a0 = 0ull, a1 = 0ull, a2 = 0ull, a3 = 0ull;
#pragma unroll
        for (int k = 0; k < 16; k++) {
            float4 q = vv[k];                       // LDS.128 broadcast
            unsigned long long p0 = pk2(q.x, q.y);
            unsigned long long p1 = pk2(q.z, q.w);
            if (k & 1) { a2 = ffma2(e2[2 * k], p0, a2); a3 = ffma2(e2[2 * k + 1], p1, a3); }
            else       { a0 = ffma2(e2[2 * k], p0, a0); a1 = ffma2(e2[2 * k + 1], p1, a1); }
        }
        unsigned long long at = fadd2(fadd2(a0, a1), fadd2(a2, a3));
        at = fadd2(at, __shfl_xor_sync(0xffffffffu, at, 1));  // combine i-halves
        if (h == 0) {
            float lo, hi; upk2(at, lo, hi);
            float w = lo + hi;
            if (smask[s]) {
                float c = sshift[(s - 1) & 1];
                float t = __logf(w) + dj + logit;
                atil = t - c;
                Z += c;
                sv[s & 1][j] = __expf(atil);
            } else {
                sv[s & 1][j] = sv[(s - 1) & 1][j];   // keep write buffer valid
            }
        }
        if (tid == 0) sshift[s & 1] = atil;
    };

    // main loop: steps 1..1020 unrolled by 4, tail 1021..1023
    for (int s = 1; s + 3 <= Sd - 4; s += 4) {
        STEP(s,     lq0); lq0 = LQ(s + 4);
        STEP(s + 1, lq1); lq1 = LQ(s + 5);
        STEP(s + 2, lq2); lq2 = LQ(s + 6);
        STEP(s + 3, lq3); lq3 = LQ(s + 7);
    }
    STEP(Sd - 3, lq0);
    STEP(Sd - 2, lq1);
    STEP(Sd - 1, lq2);
    (void)lq3;

    // ---- final: den = Z + logsumexp_j(atil_j + end_j) ----
    __syncthreads();
    if (h == 0) red[j] = atil + endt[j];
    __syncthreads();
#pragma unroll
    for (int off = 64; off > 0; off >>= 1) {
        if (tid < off) red[tid] = fmaxf(red[tid], red[tid + off]);
        __syncthreads();
    }
    float mx = red[0];
    __syncthreads();
    if (h == 0) red[j] = __expf(atil + endt[j] - mx);
    __syncthreads();
#pragma unroll
    for (int off = 64; off > 0; off >>= 1) {
        if (tid < off) red[tid] += red[tid + off];
        __syncthreads();
    }
    if (tid == 0) g_den[b] = mx + __logf(red[0]) + Z;
}

// =====================================================================
// Numerator kernel: one CTA per batch (gather + reduce).
// =====================================================================
__global__ __launch_bounds__(256, 1) void crf_num_kernel(
    const float* __restrict__ inputs,
    const int* __restrict__ tags,
    const int* __restrict__ mask,
    const float* __restrict__ trans,
    const float* __restrict__ startt,
    const float* __restrict__ endt)
{
    const int b   = blockIdx.x;
    const int tid = threadIdx.x;
    const int* tg = tags + b * Sd;
    const int* mk = mask + b * Sd;
    const float* inp = inputs + (size_t)b * Sd * Td;

    float acc = 0.f;
    int mcnt = 0;
    for (int s = tid; s < Sd; s += 256) {
        int   ms = mask_at(mk, s);
        float mf = (float)ms;
        mcnt += ms;
        int ts = tg[s];
        if (s < Sd - 1) acc += inp[s * Td + ts] * mf;           // emit[:, :-1] * mf[:, :-1]
        if (s >= 1)     acc += trans[tg[s - 1] * Td + ts] * mf; // trans * mf[:, 1:]
    }

    __shared__ float sred[256];
    __shared__ int   sredi[256];
    sred[tid] = acc; sredi[tid] = mcnt;
    __syncthreads();
#pragma unroll
    for (int off = 128; off > 0; off >>= 1) {
        if (tid < off) { sred[tid] += sred[tid + off]; sredi[tid] += sredi[tid + off]; }
        __syncthreads();
    }
    if (tid == 0) {
        int last_idx = sredi[0] - 1;
        int lt = tg[last_idx];
        float mfl = mask_at(mk, Sd - 1) ? 1.f : 0.f;
        g_num[b] = sred[0] + startt[tg[0]] + endt[lt] + inp[(Sd - 1) * Td + lt] * mfl;
    }
}

// =====================================================================
// Final reduction: out[0] = sum_b (num_b - den_b)
// =====================================================================
__global__ void crf_final_kernel(float* __restrict__ out)
{
    __shared__ float sr[Bd];
    int t = threadIdx.x;
    sr[t] = g_num[t] - g_den[t];
    __syncthreads();
#pragma unroll
    for (int off = 64; off > 0; off >>= 1) {
        if (t < off) sr[t] += sr[t + off];
        __syncthreads();
    }
    if (t == 0) out[0] = sr[0];
}

extern "C" void kernel_launch(void* const* d_in, const int* in_sizes, int n_in,
                              void* d_out, int out_size)
{
    const float* inputs = (const float*)d_in[0];
    const int*   tags   = (const int*)d_in[1];
    const int*   mask   = (const int*)d_in[2];
    const float* trans  = (const float*)d_in[3];
    const float* startt = (const float*)d_in[4];
    const float* endt   = (const float*)d_in[5];
    float* out = (float*)d_out;

    crf_den_kernel<<<Bd, 256>>>(inputs, mask, trans, startt, endt);
    crf_num_kernel<<<Bd, 256>>>(inputs, tags, mask, trans, startt, endt);
    crf_final_kernel<<<1, Bd>>>(out);
}

// round 3
// speedup vs baseline: 1.1209x; 1.1209x over previous
#include <cuda_runtime.h>
#include <cuda_bf16.h>
#include <cstdint>

// Problem constants: B=128 batches, S=1024 steps, T=128 tags.
#define Bd 128
#define Sd 1024
#define Td 128

__device__ float g_den[Bd];
__device__ float g_num[Bd];

// ---------- packed f32x2 helpers (sm_100+) ----------
__device__ __forceinline__ unsigned long long pk2(float x, float y) {
    unsigned long long r;
    asm("mov.b64 %0, {%1, %2};" : "=l"(r) : "f"(x), "f"(y));
    return r;
}
__device__ __forceinline__ void upk2(unsigned long long v, float& x, float& y) {
    asm("mov.b64 {%0, %1}, %2;" : "=f"(x), "=f"(y) : "l"(v));
}
__device__ __forceinline__ unsigned long long ffma2(unsigned long long a,
                                                    unsigned long long b,
                                                    unsigned long long c) {
    unsigned long long d;
    asm("fma.rn.f32x2 %0, %1, %2, %3;" : "=l"(d) : "l"(a), "l"(b), "l"(c));
    return d;
}
__device__ __forceinline__ unsigned long long fadd2(unsigned long long a,
                                                    unsigned long long b) {
    unsigned long long d;
    asm("add.rn.f32x2 %0, %1, %2;" : "=l"(d) : "l"(a), "l"(b));
    return d;
}

// mask arrives widened (bool -> int32/float32): nonzero 4-byte test covers both.
__device__ __forceinline__ int mask_at(const int* __restrict__ m, int idx) {
    return m[idx] != 0 ? 1 : 0;
}

// =====================================================================
// Denominator: scaled linear-space forward. One CTA per batch, 256 thr.
// Thread t: column j = t>>1, half h = t&1 (i in [64h, 64h+64)).
// E[:,j] = exp(trans[:,j] - d_j) in 32 f32x2 registers.
// Per step: w_j = sum_i sv_i E_ij ; sv'_j = w_j * u_j * r
//   u_j = exp(logit_j + d_j)  (prefetched logit -> off critical path)
//   r   = 1/sv_prev[0]        (loaded at top of step -> off critical path)
//   Z  += log(sv_prev[0])     (thread 0 only)
// No log/exp on the result-dependent path.
// =====================================================================
__global__ __launch_bounds__(256, 1) void crf_den_kernel(
    const float* __restrict__ inputs,
    const int* __restrict__ mask,
    const float* __restrict__ trans,
    const float* __restrict__ startt,
    const float* __restrict__ endt)
{
    __shared__ __align__(16) float sv[2][Td];   // scaled alpha (exp-space), ping-pong
    __shared__ unsigned char smask[Sd];
    __shared__ float red[Td];

    const int b   = blockIdx.x;
    const int tid = threadIdx.x;
    const int j   = tid >> 1;
    const int h   = tid & 1;
    const float* inp = inputs + (size_t)b * Sd * Td;

    for (int i = tid; i < Sd; i += 256)
        smask[i] = (unsigned char)mask_at(mask, b * Sd + i);

    // d_j = max_i trans[i][j]
    float dj = -1e30f;
#pragma unroll 8
    for (int i = 0; i < Td; i++) dj = fmaxf(dj, __ldg(&trans[i * Td + j]));

    // E column (own i-half) packed into f32x2 registers
    unsigned long long e2[32];
#pragma unroll
    for (int m = 0; m < 32; m++) {
        int i = h * 64 + 2 * m;
        float ea = __expf(__ldg(&trans[i * Td + j]) - dj);
        float eb = __expf(__ldg(&trans[(i + 1) * Td + j]) - dj);
        e2[m] = pk2(ea, eb);
    }

    // ---- init: sv0_j = exp(alpha0_j - alpha0_0), Z = alpha0_0 ----
    float Z = 0.f;
    {
        float a0 = startt[j] + inp[j];        // both halves compute (same value)
        if (tid == 0) red[0] = a0;            // broadcast alpha0[0]
        __syncthreads();
        float a00 = red[0];
        if (h == 0) sv[0][j] = __expf(a0 - a00);
        if (tid == 0) Z = a00;
        __syncthreads();
    }

    // logit register prefetch queue (depth 4)
    auto LQ = [&](int s) -> float {
        int sc = s < Sd ? s : (Sd - 1);
        return __ldg(&inp[sc * Td + j]);
    };
    float lq0 = LQ(1), lq1 = LQ(2), lq2 = LQ(3), lq3 = LQ(4);

    auto STEP = [&](int s, float logit) {
        const float* __restrict__ svp = sv[(s - 1) & 1];
        // off-critical-path work first: u, c, r
        float u  = __expf(logit + dj);            // MUFU, logit-only
        float c  = svp[0];                        // LDS broadcast
        float rr = __frcp_rn(c);                  // MUFU
        float vprev = svp[j];                     // for masked-copy case
        const float4* vv = reinterpret_cast<const float4*>(svp) + h * 16;
        unsigned long long a0 = 0ull, a1 = 0ull, a2 = 0ull, a3 = 0ull;
#pragma unroll
        for (int k = 0; k < 16; k++) {
            float4 q = vv[k];                     // LDS.128 broadcast
            unsigned long long p0 = pk2(q.x, q.y);
            unsigned long long p1 = pk2(q.z, q.w);
            if (k & 1) { a2 = ffma2(e2[2 * k], p0, a2); a3 = ffma2(e2[2 * k + 1], p1, a3); }
            else       { a0 = ffma2(e2[2 * k], p0, a0); a1 = ffma2(e2[2 * k + 1], p1, a1); }
        }
        unsigned long long at = fadd2(fadd2(a0, a1), fadd2(a2, a3));
        at = fadd2(at, __shfl_xor_sync(0xffffffffu, at, 1));   // both halves get full sum
        float lo, hi; upk2(at, lo, hi);
        float w = lo + hi;
        float tnew = w * u * rr;                  // two FMULs: whole epilogue
        int ms = smask[s];
        float vout = ms ? tnew : vprev;
        if (h == 0) sv[s & 1][j] = vout;
        if (tid == 0 && ms) Z += __logf(c);       // off result path
        __syncthreads();                          // publish sv[s&1] for next step
    };

    // steps 1..1023, unrolled by 4 with prefetch
    for (int s = 1; s + 3 <= Sd - 4; s += 4) {
        STEP(s,     lq0); lq0 = LQ(s + 4);
        STEP(s + 1, lq1); lq1 = LQ(s + 5);
        STEP(s + 2, lq2); lq2 = LQ(s + 6);
        STEP(s + 3, lq3); lq3 = LQ(s + 7);
    }
    STEP(Sd - 3, lq0);
    STEP(Sd - 2, lq1);
    STEP(Sd - 1, lq2);
    (void)lq3;

    // ---- final: den = Z + log( sum_j sv_j * exp(end_j) ) ----
    // (sv values are bounded by per-step rescale; direct sum is safe in fp32)
    if (h == 0) red[j] = sv[(Sd - 1) & 1][j] * __expf(endt[j]);
    __syncthreads();
#pragma unroll
    for (int off = 64; off > 0; off >>= 1) {
        if (tid < off) red[tid] += red[tid + off];
        __syncthreads();
    }
    if (tid == 0) g_den[b] = Z + __logf(red[0]);
}

// =====================================================================
// Numerator kernel: one CTA per batch (gather + reduce).
// =====================================================================
__global__ __launch_bounds__(256, 1) void crf_num_kernel(
    const float* __restrict__ inputs,
    const int* __restrict__ tags,
    const int* __restrict__ mask,
    const float* __restrict__ trans,
    const float* __restrict__ startt,
    const float* __restrict__ endt)
{
    const int b   = blockIdx.x;
    const int tid = threadIdx.x;
    const int* tg = tags + b * Sd;
    const int* mk = mask + b * Sd;
    const float* inp = inputs + (size_t)b * Sd * Td;

    float acc = 0.f;
    int mcnt = 0;
    for (int s = tid; s < Sd; s += 256) {
        int   ms = mask_at(mk, s);
        float mf = (float)ms;
        mcnt += ms;
        int ts = tg[s];
        if (s < Sd - 1) acc += inp[s * Td + ts] * mf;
        if (s >= 1)     acc += trans[tg[s - 1] * Td + ts] * mf;
    }

    __shared__ float sred[256];
    __shared__ int   sredi[256];
    sred[tid] = acc; sredi[tid] = mcnt;
    __syncthreads();
#pragma unroll
    for (int off = 128; off > 0; off >>= 1) {
        if (tid < off) { sred[tid] += sred[tid + off]; sredi[tid] += sredi[tid + off]; }
        __syncthreads();
    }
    if (tid == 0) {
        int last_idx = sredi[0] - 1;
        int lt = tg[last_idx];
        float mfl = mask_at(mk, Sd - 1) ? 1.f : 0.f;
        g_num[b] = sred[0] + startt[tg[0]] + endt[lt] + inp[(Sd - 1) * Td + lt] * mfl;
    }
}

// =====================================================================
// Final reduction: out[0] = sum_b (num_b - den_b)
// =====================================================================
__global__ void crf_final_kernel(float* __restrict__ out)
{
    __shared__ float sr[Bd];
    int t = threadIdx.x;
    sr[t] = g_num[t] - g_den[t];
    __syncthreads();
#pragma unroll
    for (int off = 64; off > 0; off >>= 1) {
        if (t < off) sr[t] += sr[t + off];
        __syncthreads();
    }
    if (t == 0) out[0] = sr[0];
}

extern "C" void kernel_launch(void* const* d_in, const int* in_sizes, int n_in,
                              void* d_out, int out_size)
{
    const float* inputs = (const float*)d_in[0];
    const int*   tags   = (const int*)d_in[1];
    const int*   mask   = (const int*)d_in[2];
    const float* trans  = (const float*)d_in[3];
    const float* startt = (const float*)d_in[4];
    const float* endt   = (const float*)d_in[5];
    float* out = (float*)d_out;

    crf_den_kernel<<<Bd, 256>>>(inputs, mask, trans, startt, endt);
    crf_num_kernel<<<Bd, 256>>>(inputs, tags, mask, trans, startt, endt);
    crf_final_kernel<<<1, Bd>>>(out);
}